// round 6
// baseline (speedup 1.0000x reference)
#include <cuda_runtime.h>
#include <cuda_bf16.h>

// Downsampler: (16,8,1024,1024) fp32, 4x4 Gaussian kernel, stride 4, VALID.
// Output (16,8,256,256) fp32. Pure streaming (each input read once).
// R6 (= R3 retry #3, unchanged): persistent grid-stride kernel + streaming
// cache hints (__ldcs/__stcs), weights hoisted, x2 unroll (MLP=8).
// GB300 has 152 SMs -> 152x8 CTAs.

#define N_  16
#define C_  8
#define H_  1024
#define W_  1024
#define F_  4
#define HO_ (H_ / F_)   // 256
#define WO_ (W_ / F_)   // 256
#define W4_ (W_ / 4)    // 256 float4 per input row
#define TOTAL_ (N_ * C_ * HO_ * WO_)   // 16,777,216 outputs

__global__ __launch_bounds__(256) void Downsampler_24421184045082_kernel(
    const float* __restrict__ x,
    const float* __restrict__ kern,
    float* __restrict__ out,
    int nthreads)
{
    // Weights: loaded once per thread, outside the loop.
    float k00 = __ldg(kern + 0),  k01 = __ldg(kern + 1),  k02 = __ldg(kern + 2),  k03 = __ldg(kern + 3);
    float k10 = __ldg(kern + 4),  k11 = __ldg(kern + 5),  k12 = __ldg(kern + 6),  k13 = __ldg(kern + 7);
    float k20 = __ldg(kern + 8),  k21 = __ldg(kern + 9),  k22 = __ldg(kern + 10), k23 = __ldg(kern + 11);
    float k30 = __ldg(kern + 12), k31 = __ldg(kern + 13), k32 = __ldg(kern + 14), k33 = __ldg(kern + 15);

    const float4* x4 = reinterpret_cast<const float4*>(x);
    int tid = blockIdx.x * blockDim.x + threadIdx.x;

#pragma unroll 2
    for (int o = tid; o < TOTAL_; o += nthreads) {
        // o = ((nc*HO)+oh)*WO + ow ; all power-of-2 -> bit ops.
        // Patch base (in float4 units): ow | oh*4*W4 | nc*H*W4
        //   = (o & 255) | ((o>>8 & 255) << 10) | ((o>>16) << 18)
        int base = (o & 0xFF) | ((o & 0xFF00) << 2) | ((o >> 16) << 18);

        // 4 independent row loads, streaming (evict-first) policy.
        float4 r0 = __ldcs(x4 + base + 0 * W4_);
        float4 r1 = __ldcs(x4 + base + 1 * W4_);
        float4 r2 = __ldcs(x4 + base + 2 * W4_);
        float4 r3 = __ldcs(x4 + base + 3 * W4_);

        float acc;
        acc  = k00 * r0.x + k01 * r0.y + k02 * r0.z + k03 * r0.w;
        acc += k10 * r1.x + k11 * r1.y + k12 * r1.z + k13 * r1.w;
        acc += k20 * r2.x + k21 * r2.y + k22 * r2.z + k23 * r2.w;
        acc += k30 * r3.x + k31 * r3.y + k32 * r3.z + k33 * r3.w;

        __stcs(out + o, acc);
    }
}

extern "C" void kernel_launch(void* const* d_in, const int* in_sizes, int n_in,
                              void* d_out, int out_size)
{
    const float* x    = (const float*)d_in[0];   // (16,8,1024,1024) fp32
    const float* kern = (const float*)d_in[1];   // (4,4) fp32
    float* out = (float*)d_out;                  // (16,8,256,256) fp32

    // Persistent fill: 152 SMs x 8 CTAs (32 regs, 256 thr -> occ 8/SM).
    int blocks = 152 * 8;                        // 1216
    int threads = 256;
    int nthreads = blocks * threads;             // 311,296
    Downsampler_24421184045082_kernel<<<blocks, threads>>>(x, kern, out, nthreads);
}

// round 7
// speedup vs baseline: 1.1143x; 1.1143x over previous
#include <cuda_runtime.h>
#include <cuda_bf16.h>

// Downsampler: (16,8,1024,1024) fp32, 4x4 Gaussian kernel, stride 4, VALID.
// Output (16,8,256,256) fp32. Non-overlapping windows -> pure streaming.
// R7: exactly R1 (best: 84.3us) + streaming cache policy on the bulk
// traffic (__ldcs for input rows, __stcs for output). Single-change test.

#define N_  16
#define C_  8
#define H_  1024
#define W_  1024
#define F_  4
#define HO_ (H_ / F_)   // 256
#define WO_ (W_ / F_)   // 256

__global__ __launch_bounds__(256) void Downsampler_24421184045082_kernel(
    const float* __restrict__ x,
    const float* __restrict__ kern,
    float* __restrict__ out,
    int total)
{
    int o = blockIdx.x * blockDim.x + threadIdx.x;
    if (o >= total) return;

    // Decompose output index: o = ((nc * HO) + oh) * WO + ow
    int ow = o & (WO_ - 1);            // 256 = 2^8
    int oh = (o >> 8) & (HO_ - 1);
    int nc = o >> 16;

    // Weights: reused by every thread -> keep default caching (__ldg).
    float k00 = __ldg(kern + 0),  k01 = __ldg(kern + 1),  k02 = __ldg(kern + 2),  k03 = __ldg(kern + 3);
    float k10 = __ldg(kern + 4),  k11 = __ldg(kern + 5),  k12 = __ldg(kern + 6),  k13 = __ldg(kern + 7);
    float k20 = __ldg(kern + 8),  k21 = __ldg(kern + 9),  k22 = __ldg(kern + 10), k23 = __ldg(kern + 11);
    float k30 = __ldg(kern + 12), k31 = __ldg(kern + 13), k32 = __ldg(kern + 14), k33 = __ldg(kern + 15);

    // Base of this thread's 4x4 patch, viewed as float4 rows.
    const float4* x4 = reinterpret_cast<const float4*>(x)
                     + (size_t)nc * (H_ * (W_ / 4))
                     + (size_t)(oh * F_) * (W_ / 4)
                     + ow;

    // 4 independent row loads, evict-first streaming policy (single-use data).
    float4 r0 = __ldcs(x4 + 0 * (W_ / 4));
    float4 r1 = __ldcs(x4 + 1 * (W_ / 4));
    float4 r2 = __ldcs(x4 + 2 * (W_ / 4));
    float4 r3 = __ldcs(x4 + 3 * (W_ / 4));

    float acc;
    acc  = k00 * r0.x + k01 * r0.y + k02 * r0.z + k03 * r0.w;
    acc += k10 * r1.x + k11 * r1.y + k12 * r1.z + k13 * r1.w;
    acc += k20 * r2.x + k21 * r2.y + k22 * r2.z + k23 * r2.w;
    acc += k30 * r3.x + k31 * r3.y + k32 * r3.z + k33 * r3.w;

    __stcs(out + o, acc);
}

extern "C" void kernel_launch(void* const* d_in, const int* in_sizes, int n_in,
                              void* d_out, int out_size)
{
    const float* x    = (const float*)d_in[0];   // (16,8,1024,1024) fp32
    const float* kern = (const float*)d_in[1];   // (4,4) fp32
    float* out = (float*)d_out;                  // (16,8,256,256) fp32

    int total = N_ * C_ * HO_ * WO_;             // 16,777,216
    int threads = 256;
    int blocks = (total + threads - 1) / threads; // 65536
    Downsampler_24421184045082_kernel<<<blocks, threads>>>(x, kern, out, total);
}